// round 13
// baseline (speedup 1.0000x reference)
#include <cuda_runtime.h>
#include <cuda_fp16.h>
#include <math.h>
#include <stdint.h>

// Problem constants
#define D_MODEL 2048
#define N_HEADS 16
#define HEAD_D  128
#define BATCH   2
#define SEQ     2048
#define M_TOT   (BATCH * SEQ)   // 4096
#define QKV_N   (3 * D_MODEL)   // 6144

// Scratch (allocation-free: __device__ globals), all fp16
__device__ __half g_qkv[(size_t)M_TOT * QKV_N];
__device__ __half g_att[(size_t)M_TOT * D_MODEL];
__device__ __half g_xh[(size_t)M_TOT * D_MODEL];
__device__ __half g_wqkvh[(size_t)D_MODEL * QKV_N];
__device__ __half g_woh[(size_t)D_MODEL * D_MODEL];

// ---------------------------------------------------------------------------
// helpers
// ---------------------------------------------------------------------------
__device__ __forceinline__ uint32_t pack2(float a, float b) {
    __half2 h = __floats2half2_rn(a, b);
    return *(uint32_t*)&h;
}

__device__ __forceinline__ float ex2f(float x) {
    float r;
    asm("ex2.approx.ftz.f32 %0, %1;" : "=f"(r) : "f"(x));
    return r;
}

// packed 2^x on half2 (one MUFU op for two values)
__device__ __forceinline__ uint32_t h2exp2_bits(float a, float b) {
    uint32_t u = pack2(a, b);
    asm("ex2.approx.f16x2 %0, %0;" : "+r"(u));
    return u;
}

__device__ __forceinline__ void mma_f16(float d[4], const uint32_t a[4],
                                        const uint32_t b[2]) {
    asm volatile(
        "mma.sync.aligned.m16n8k16.row.col.f32.f16.f16.f32 "
        "{%0,%1,%2,%3}, {%4,%5,%6,%7}, {%8,%9}, {%0,%1,%2,%3};"
        : "+f"(d[0]), "+f"(d[1]), "+f"(d[2]), "+f"(d[3])
        : "r"(a[0]), "r"(a[1]), "r"(a[2]), "r"(a[3]),
          "r"(b[0]), "r"(b[1]));
}

#define LDSM_X4(r0, r1, r2, r3, addr) \
    asm volatile("ldmatrix.sync.aligned.m8n8.x4.shared.b16 {%0,%1,%2,%3}, [%4];" \
                 : "=r"(r0), "=r"(r1), "=r"(r2), "=r"(r3) : "r"(addr))
#define LDSM_X4_T(r0, r1, r2, r3, addr) \
    asm volatile("ldmatrix.sync.aligned.m8n8.x4.trans.shared.b16 {%0,%1,%2,%3}, [%4];" \
                 : "=r"(r0), "=r"(r1), "=r"(r2), "=r"(r3) : "r"(addr))

#define CP_ASYNC16(dst, src) \
    asm volatile("cp.async.cg.shared.global [%0], [%1], 16;" :: "r"(dst), "l"(src))
#define CP_COMMIT() asm volatile("cp.async.commit_group;" ::: "memory")
#define CP_WAIT1()  asm volatile("cp.async.wait_group 1;" ::: "memory")
#define CP_WAIT0()  asm volatile("cp.async.wait_group 0;" ::: "memory")

__device__ __forceinline__ uint32_t smem_u32(const void* p) {
    uint32_t a;
    asm("{ .reg .u64 t; cvta.to.shared.u64 t, %1; cvt.u32.u64 %0, t; }"
        : "=r"(a) : "l"(p));
    return a;
}

// ---------------------------------------------------------------------------
// fp32 -> fp16 convert kernel (float4 -> 8 bytes)
// ---------------------------------------------------------------------------
__global__ void to_f16(const float4* __restrict__ src, uint2* __restrict__ dst,
                       int n4) {
    int i = blockIdx.x * blockDim.x + threadIdx.x;
    if (i < n4) {
        float4 v = src[i];
        uint2 o;
        o.x = pack2(v.x, v.y);
        o.y = pack2(v.z, v.w);
        dst[i] = o;
    }
}

// ---------------------------------------------------------------------------
// fp16 GEMM (fp32 accum), cp.async 3-stage, 1 sync/ktile. (unchanged)
// CTA 128x128, BK=64, 256 thr = 8 warps (2x4), warp tile 64x32.
// ---------------------------------------------------------------------------
#define GASZ  16384            // 128 * 128B
#define GBSZ  16384            // 64 * 256B
#define GSTG  (GASZ + GBSZ)    // 32768
#define GEMM_SMEM (3 * GSTG)   // 98304

__global__ __launch_bounds__(256, 2) void gemm_f16(const __half* __restrict__ A,
                                                   const __half* __restrict__ Bm,
                                                   void* __restrict__ Cv,
                                                   int M, int N, int K, int outhalf) {
    extern __shared__ char sm[];
    const uint32_t sbase = smem_u32(sm);

    const int tid  = threadIdx.x;
    const int lane = tid & 31;
    const int warp = tid >> 5;
    const int g    = lane >> 2;
    const int tg   = lane & 3;
    const int wm   = warp >> 2;  // 0..1
    const int wn   = warp & 3;   // 0..3
    const int row0 = blockIdx.y * 128;
    const int col0 = blockIdx.x * 128;
    const int NT   = K >> 6;

    const int lm_r  = (lane & 7) + (lane & 8);
    const int lm_hi = (lane >> 4) & 1;
    const int lm_x  = (lane & 7) << 4;
    const int bt_r  = lane & 7;
    const int bt_kh = (lane >> 3) & 1;
    const int bt_nj = lane >> 4;

    float acc[4][4][4];
#pragma unroll
    for (int i = 0; i < 4; i++)
#pragma unroll
        for (int j = 0; j < 4; j++)
#pragma unroll
            for (int r = 0; r < 4; r++) acc[i][j][r] = 0.f;

    auto stage_cp = [&](int kt, int s) {
        const uint32_t as = sbase + s * GSTG;
        const uint32_t bs = as + GASZ;
        const __half* Ag = A + (size_t)row0 * K + kt * 64;
#pragma unroll
        for (int i = 0; i < 4; i++) {
            int idx = tid + 256 * i;
            int m = idx >> 3;
            int c = idx & 7;
            CP_ASYNC16(as + m * 128 + ((c << 4) ^ ((m & 7) << 4)),
                       Ag + (size_t)m * K + c * 8);
        }
        const __half* Bg = Bm + (size_t)(kt * 64) * N + col0;
#pragma unroll
        for (int i = 0; i < 4; i++) {
            int idx = tid + 256 * i;
            int r = idx >> 4;
            int c = idx & 15;
            CP_ASYNC16(bs + r * 256 + ((c << 4) ^ ((r & 7) << 4)),
                       Bg + (size_t)r * N + c * 8);
        }
    };

    stage_cp(0, 0); CP_COMMIT();
    if (NT > 1) stage_cp(1, 1);
    CP_COMMIT();

    int s = 0, s2 = 2;
    for (int kt = 0; kt < NT; kt++) {
        CP_WAIT1();
        __syncthreads();
        if (kt + 2 < NT) stage_cp(kt + 2, s2);
        CP_COMMIT();

        const uint32_t as = sbase + s * GSTG;
        const uint32_t bs = as + GASZ;
#pragma unroll
        for (int ks = 0; ks < 4; ks++) {
            uint32_t a[4][4];
#pragma unroll
            for (int mi = 0; mi < 4; mi++) {
                int mrow = wm * 64 + mi * 16 + lm_r;
                uint32_t addr = as + mrow * 128 + (((2 * ks + lm_hi) << 4) ^ lm_x);
                LDSM_X4(a[mi][0], a[mi][1], a[mi][2], a[mi][3], addr);
            }
#pragma unroll
            for (int njp = 0; njp < 2; njp++) {
                int kr = ks * 16 + bt_kh * 8 + bt_r;
                int cn = wn * 4 + 2 * njp + bt_nj;
                uint32_t addr = bs + kr * 256 + ((cn << 4) ^ (bt_r << 4));
                uint32_t b[2][2];
                LDSM_X4_T(b[0][0], b[0][1], b[1][0], b[1][1], addr);
#pragma unroll
                for (int mi = 0; mi < 4; mi++) {
                    mma_f16(acc[mi][2 * njp], a[mi], b[0]);
                    mma_f16(acc[mi][2 * njp + 1], a[mi], b[1]);
                }
            }
        }
        s = (s + 1) % 3;
        s2 = (s2 + 1) % 3;
    }

    if (outhalf) {
        __half* C = (__half*)Cv;
#pragma unroll
        for (int mi = 0; mi < 4; mi++)
#pragma unroll
            for (int nj = 0; nj < 4; nj++) {
                int r = row0 + wm * 64 + mi * 16 + g;
                int c = col0 + wn * 32 + nj * 8 + 2 * tg;
                *(uint32_t*)(C + (size_t)r * N + c) = pack2(acc[mi][nj][0], acc[mi][nj][1]);
                *(uint32_t*)(C + (size_t)(r + 8) * N + c) = pack2(acc[mi][nj][2], acc[mi][nj][3]);
            }
    } else {
        float* C = (float*)Cv;
#pragma unroll
        for (int mi = 0; mi < 4; mi++)
#pragma unroll
            for (int nj = 0; nj < 4; nj++) {
                int r = row0 + wm * 64 + mi * 16 + g;
                int c = col0 + wn * 32 + nj * 8 + 2 * tg;
                *(float2*)(C + (size_t)r * N + c) = make_float2(acc[mi][nj][0], acc[mi][nj][1]);
                *(float2*)(C + (size_t)(r + 8) * N + c) = make_float2(acc[mi][nj][2], acc[mi][nj][3]);
            }
    }
}

// ---------------------------------------------------------------------------
// Flash attention fp16, log2-domain softmax with ex2.approx.f16x2.
// Scores carry scale*log2(e); p = 2^(s-m) computed as packed half2 (which IS
// the PV A-fragment layout -> zero pack cost). Row sums unpack the same fp16
// p values (numerator/denominator consistent).
// ---------------------------------------------------------------------------
#define OFFQ 0
#define OFFK 16384
#define OFFV 32768
#define ATT_SMEM 49152
#define OW 130
#define EXW (32 * OW + 64)
#define MASKVAL (-30000.0f)

__global__ __launch_bounds__(128, 2) void attn_f16(const __half* __restrict__ qkv,
                                                   __half* __restrict__ o) {
    extern __shared__ char sm[];
    const uint32_t sbase = smem_u32(sm);

    const int tid  = threadIdx.x;
    const int lane = tid & 31;
    const int warp = tid >> 5;    // 0..3
    const int g    = lane >> 2;
    const int tg   = lane & 3;
    const int wq   = warp >> 1;   // 0..1 row group
    const int wk   = warp & 1;    // 0..1 key half

    const int lm_r  = (lane & 7) + (lane & 8);
    const int lm_hi = (lane >> 4) & 1;
    const int lm_x  = (lane & 7) << 4;
    const int bt_r  = lane & 7;
    const int bt_kh = (lane >> 3) & 1;
    const int bt_nj = lane >> 4;

    const int bh = blockIdx.x;
    const int b  = bh >> 4;
    const int h  = bh & 15;
    const int qt = (int)gridDim.y - 1 - (int)blockIdx.y;
    const int q0 = qt * 64;
    // scale * log2(e): scores live in the log2 domain
    const float scale2 = 0.08838834764831845f * 1.4426950408889634f;

    const __half* qb = qkv + (size_t)b * SEQ * QKV_N + h * HEAD_D;
    const __half* kb = qb + D_MODEL;
    const __half* vb = qb + 2 * D_MODEL;

    auto stage_k = [&](int kt) {
        const int k0 = kt * 64;
#pragma unroll
        for (int i = 0; i < 8; i++) {
            int idx = tid + 128 * i;
            int r = idx >> 4;
            int c = idx & 15;
            CP_ASYNC16(sbase + OFFK + r * 256 + ((c << 4) ^ ((r & 7) << 4)),
                       kb + (size_t)(k0 + r) * QKV_N + c * 8);
        }
    };
    auto stage_v = [&](int kt) {
        const int k0 = kt * 64;
#pragma unroll
        for (int i = 0; i < 8; i++) {
            int idx = tid + 128 * i;
            int r = idx >> 4;
            int c = idx & 15;
            CP_ASYNC16(sbase + OFFV + r * 256 + ((c << 4) ^ ((r & 7) << 4)),
                       vb + (size_t)(k0 + r) * QKV_N + c * 8);
        }
    };

    // Prologue: Q + K0 + V0
#pragma unroll
    for (int i = 0; i < 8; i++) {
        int idx = tid + 128 * i;
        int r = idx >> 4;
        int c = idx & 15;
        CP_ASYNC16(sbase + OFFQ + r * 256 + ((c << 4) ^ ((r & 7) << 4)),
                   qb + (size_t)(q0 + r) * QKV_N + c * 8);
    }
    stage_k(0);
    stage_v(0);
    CP_COMMIT();

    float m[2][2], l[2][2];
#pragma unroll
    for (int mi = 0; mi < 2; mi++) { m[mi][0] = m[mi][1] = 0.f; l[mi][0] = l[mi][1] = 0.f; }
    float oacc[2][16][4];
#pragma unroll
    for (int mi = 0; mi < 2; mi++)
#pragma unroll
        for (int nj = 0; nj < 16; nj++)
#pragma unroll
            for (int c = 0; c < 4; c++) oacc[mi][nj][c] = 0.f;

    for (int kt = 0; kt <= qt; kt++) {
        const int k0 = kt * 64;
        if (kt == 0) { CP_WAIT0(); } else { CP_WAIT1(); }
        __syncthreads();

        // S = Q(32x128) @ K_half^T(32 keys)
        float s[2][4][4];
#pragma unroll
        for (int mi = 0; mi < 2; mi++)
#pragma unroll
            for (int nj = 0; nj < 4; nj++)
#pragma unroll
                for (int c = 0; c < 4; c++) s[mi][nj][c] = 0.f;

#pragma unroll
        for (int ks = 0; ks < 8; ks++) {
            uint32_t a[2][4];
#pragma unroll
            for (int mi = 0; mi < 2; mi++) {
                int rr = wq * 32 + mi * 16 + lm_r;
                uint32_t addr = sbase + OFFQ + rr * 256 + (((2 * ks + lm_hi) << 4) ^ lm_x);
                LDSM_X4(a[mi][0], a[mi][1], a[mi][2], a[mi][3], addr);
            }
#pragma unroll
            for (int njp = 0; njp < 2; njp++) {
                int key = wk * 32 + (2 * njp + bt_nj) * 8 + bt_r;
                int ch = 2 * ks + bt_kh;
                uint32_t addr = sbase + OFFK + key * 256 + ((ch << 4) ^ (bt_r << 4));
                uint32_t bq[2][2];
                LDSM_X4(bq[0][0], bq[0][1], bq[1][0], bq[1][1], addr);
#pragma unroll
                for (int mi = 0; mi < 2; mi++) {
                    mma_f16(s[mi][2 * njp], a[mi], bq[0]);
                    mma_f16(s[mi][2 * njp + 1], a[mi], bq[1]);
                }
            }
        }

        // scale (log2 domain) + causal mask + warp-local row max
        const bool diag = (kt == qt);
        float pm[2][2];
        pm[0][0] = pm[0][1] = pm[1][0] = pm[1][1] = -3.0e38f;
#pragma unroll
        for (int mi = 0; mi < 2; mi++) {
            const int rg0 = q0 + wq * 32 + mi * 16 + g;
            const int rg1 = rg0 + 8;
#pragma unroll
            for (int nj = 0; nj < 4; nj++) {
                int c = k0 + wk * 32 + nj * 8 + 2 * tg;
                float v0 = s[mi][nj][0] * scale2;
                float v1 = s[mi][nj][1] * scale2;
                float v2 = s[mi][nj][2] * scale2;
                float v3 = s[mi][nj][3] * scale2;
                if (diag) {
                    if (c > rg0) v0 = MASKVAL;
                    if (c + 1 > rg0) v1 = MASKVAL;
                    if (c > rg1) v2 = MASKVAL;
                    if (c + 1 > rg1) v3 = MASKVAL;
                }
                s[mi][nj][0] = v0; s[mi][nj][1] = v1;
                s[mi][nj][2] = v2; s[mi][nj][3] = v3;
                pm[mi][0] = fmaxf(pm[mi][0], fmaxf(v0, v1));
                pm[mi][1] = fmaxf(pm[mi][1], fmaxf(v2, v3));
            }
        }
#pragma unroll
        for (int mi = 0; mi < 2; mi++) {
            pm[mi][0] = fmaxf(pm[mi][0], __shfl_xor_sync(0xffffffffu, pm[mi][0], 1));
            pm[mi][0] = fmaxf(pm[mi][0], __shfl_xor_sync(0xffffffffu, pm[mi][0], 2));
            pm[mi][1] = fmaxf(pm[mi][1], __shfl_xor_sync(0xffffffffu, pm[mi][1], 1));
            pm[mi][1] = fmaxf(pm[mi][1], __shfl_xor_sync(0xffffffffu, pm[mi][1], 2));
        }

        // V(kt) ready + all warps past K reads -> restage K
        CP_WAIT0();
        __syncthreads();
        if (kt < qt) { stage_k(kt + 1); CP_COMMIT(); }

        float alpha[2][2];
#pragma unroll
        for (int mi = 0; mi < 2; mi++)
#pragma unroll
            for (int hh = 0; hh < 2; hh++) {
                float mn = fmaxf(m[mi][hh], pm[mi][hh]);
                alpha[mi][hh] = ex2f(m[mi][hh] - mn);
                m[mi][hh] = mn;
            }

        // p = 2^(s - m) as packed half2 (PV A-fragment layout); row sums from
        // the SAME fp16 values (consistent numerator/denominator).
        uint32_t ph_lo[2][4], ph_hi[2][4];
        float ps[2][2];
        ps[0][0] = ps[0][1] = ps[1][0] = ps[1][1] = 0.f;
#pragma unroll
        for (int mi = 0; mi < 2; mi++)
#pragma unroll
            for (int nj = 0; nj < 4; nj++) {
                uint32_t plo = h2exp2_bits(s[mi][nj][0] - m[mi][0], s[mi][nj][1] - m[mi][0]);
                uint32_t phi = h2exp2_bits(s[mi][nj][2] - m[mi][1], s[mi][nj][3] - m[mi][1]);
                ph_lo[mi][nj] = plo;
                ph_hi[mi][nj] = phi;
                float2 f0 = __half22float2(*(__half2*)&plo);
                float2 f1 = __half22float2(*(__half2*)&phi);
                ps[mi][0] += f0.x + f0.y;
                ps[mi][1] += f1.x + f1.y;
            }
#pragma unroll
        for (int mi = 0; mi < 2; mi++)
#pragma unroll
            for (int hh = 0; hh < 2; hh++) {
                float p = ps[mi][hh];
                p += __shfl_xor_sync(0xffffffffu, p, 1);
                p += __shfl_xor_sync(0xffffffffu, p, 2);
                l[mi][hh] = l[mi][hh] * alpha[mi][hh] + p;
            }

        // rescale O
#pragma unroll
        for (int mi = 0; mi < 2; mi++)
#pragma unroll
            for (int nj = 0; nj < 16; nj++) {
                oacc[mi][nj][0] *= alpha[mi][0]; oacc[mi][nj][1] *= alpha[mi][0];
                oacc[mi][nj][2] *= alpha[mi][1]; oacc[mi][nj][3] *= alpha[mi][1];
            }

        // O += P(32x32) @ V_half(32x128): fragments are ph_lo/ph_hi directly
#pragma unroll
        for (int ks = 0; ks < 2; ks++) {
            uint32_t a[2][4];
#pragma unroll
            for (int mi = 0; mi < 2; mi++) {
                a[mi][0] = ph_lo[mi][2 * ks];
                a[mi][1] = ph_hi[mi][2 * ks];
                a[mi][2] = ph_lo[mi][2 * ks + 1];
                a[mi][3] = ph_hi[mi][2 * ks + 1];
            }
#pragma unroll
            for (int vp = 0; vp < 8; vp++) {
                int key = wk * 32 + ks * 16 + bt_kh * 8 + bt_r;
                int cn = 2 * vp + bt_nj;
                uint32_t addr = sbase + OFFV + key * 256 + ((cn << 4) ^ (bt_r << 4));
                uint32_t bv[2][2];
                LDSM_X4_T(bv[0][0], bv[0][1], bv[1][0], bv[1][1], addr);
                mma_f16(oacc[0][2 * vp], a[0], bv[0]);
                mma_f16(oacc[1][2 * vp], a[1], bv[0]);
                mma_f16(oacc[0][2 * vp + 1], a[0], bv[1]);
                mma_f16(oacc[1][2 * vp + 1], a[1], bv[1]);
            }
        }

        // all warps done reading V(kt) -> restage V
        if (kt < qt) {
            __syncthreads();
            stage_v(kt + 1);
            CP_COMMIT();
        }
    }

    // ---- combine the two wk halves (log2 domain) ----
    __syncthreads();
    float* ex = (float*)sm + wq * EXW;
    if (wk) {
#pragma unroll
        for (int mi = 0; mi < 2; mi++)
#pragma unroll
            for (int nj = 0; nj < 16; nj++) {
                int cc = nj * 8 + 2 * tg;
                int lr0 = g + 16 * mi;
                *(float2*)&ex[lr0 * OW + cc] = make_float2(oacc[mi][nj][0], oacc[mi][nj][1]);
                *(float2*)&ex[(lr0 + 8) * OW + cc] = make_float2(oacc[mi][nj][2], oacc[mi][nj][3]);
            }
        if (tg == 0) {
#pragma unroll
            for (int mi = 0; mi < 2; mi++)
#pragma unroll
                for (int hh = 0; hh < 2; hh++) {
                    ex[32 * OW + mi * 16 + hh * 8 + g] = m[mi][hh];
                    ex[32 * OW + 32 + mi * 16 + hh * 8 + g] = l[mi][hh];
                }
        }
    }
    __syncthreads();
    if (!wk) {
#pragma unroll
        for (int mi = 0; mi < 2; mi++) {
#pragma unroll
            for (int hh = 0; hh < 2; hh++) {
                float mp = ex[32 * OW + mi * 16 + hh * 8 + g];
                float lp = ex[32 * OW + 32 + mi * 16 + hh * 8 + g];
                float M  = fmaxf(m[mi][hh], mp);
                float fo = ex2f(m[mi][hh] - M);
                float fp = ex2f(mp - M);
                float inv = 1.0f / (l[mi][hh] * fo + lp * fp);
                const int rowg = q0 + wq * 32 + 16 * mi + 8 * hh + g;
                const int lr   = g + 16 * mi + 8 * hh;
#pragma unroll
                for (int nj = 0; nj < 16; nj++) {
                    int cc = nj * 8 + 2 * tg;
                    float2 qv = *(float2*)&ex[lr * OW + cc];
                    float a0 = oacc[mi][nj][2 * hh + 0];
                    float a1 = oacc[mi][nj][2 * hh + 1];
                    float v0 = (a0 * fo + qv.x * fp) * inv;
                    float v1 = (a1 * fo + qv.y * fp) * inv;
                    __half* dp = o + (size_t)(b * SEQ + rowg) * D_MODEL + h * HEAD_D + cc;
                    *(uint32_t*)dp = pack2(v0, v1);
                }
            }
        }
    }
}

// ---------------------------------------------------------------------------
extern "C" void kernel_launch(void* const* d_in, const int* in_sizes, int n_in,
                              void* d_out, int out_size) {
    const float* x    = (const float*)d_in[0];
    const float* Wqkv = (const float*)d_in[1];
    const float* Wo   = (const float*)d_in[2];
    float* out = (float*)d_out;

    __half *qkv_p, *att_p, *xh_p, *wqkvh_p, *woh_p;
    cudaGetSymbolAddress((void**)&qkv_p, g_qkv);
    cudaGetSymbolAddress((void**)&att_p, g_att);
    cudaGetSymbolAddress((void**)&xh_p, g_xh);
    cudaGetSymbolAddress((void**)&wqkvh_p, g_wqkvh);
    cudaGetSymbolAddress((void**)&woh_p, g_woh);

    cudaFuncSetAttribute(gemm_f16, cudaFuncAttributeMaxDynamicSharedMemorySize, GEMM_SMEM);
    cudaFuncSetAttribute(attn_f16, cudaFuncAttributeMaxDynamicSharedMemorySize, ATT_SMEM);

    // 0) convert inputs to fp16
    {
        int n4x = M_TOT * D_MODEL / 4;
        int n4q = D_MODEL * QKV_N / 4;
        int n4o = D_MODEL * D_MODEL / 4;
        to_f16<<<(n4x + 255) / 256, 256>>>((const float4*)x, (uint2*)xh_p, n4x);
        to_f16<<<(n4q + 255) / 256, 256>>>((const float4*)Wqkv, (uint2*)wqkvh_p, n4q);
        to_f16<<<(n4o + 255) / 256, 256>>>((const float4*)Wo, (uint2*)woh_p, n4o);
    }

    // 1) QKV projection (fp16 out)
    gemm_f16<<<dim3(QKV_N / 128, M_TOT / 128), dim3(256), GEMM_SMEM>>>(
        xh_p, wqkvh_p, qkv_p, M_TOT, QKV_N, D_MODEL, 1);

    // 2) Causal flash attention (fp16, log2-domain softmax)
    attn_f16<<<dim3(BATCH * N_HEADS, SEQ / 64), dim3(128), ATT_SMEM>>>(qkv_p, att_p);

    // 3) Output projection (fp32 out)
    gemm_f16<<<dim3(D_MODEL / 128, M_TOT / 128), dim3(256), GEMM_SMEM>>>(
        att_p, woh_p, out, M_TOT, D_MODEL, D_MODEL, 0);
}